// round 12
// baseline (speedup 1.0000x reference)
#include <cuda_runtime.h>
#include <cuda_bf16.h>
#include <cstddef>

// FM layer:
//   idx[b,j] = N_DENSE + j*PER_FIELD + sparse[b,j]
//   first[b] = w0 + dense[b,:]·w[:13] + sum_j w[idx[b,j]]
//   e_k[b]   = dense[b,:]·V[k,:13] + sum_j V[k, idx[b,j]]
//   sq_k[b]  = (dense[b,:]^2)·(V[k,:13]^2) + sum_j V[k, idx[b,j]]^2
//   out[b]   = first[b] + 0.5 * sum_k (e_k^2 - sq_k)
//
// Inputs (metadata order):
//   d_in[0] dense  f32 [4096,13]
//   d_in[1] sparse i32 [4096,26]
//   d_in[2] w0     f32 [1]
//   d_in[3] w      f32 [2600013,1]
//   d_in[4] V      f32 [16,2600013]
// Output: f32 [4096,1]

#define FM_BATCH     4096
#define FM_NDENSE    13
#define FM_NFIELDS   26
#define FM_PERFIELD  100000
#define FM_FEATNUM   2600013
#define FM_K         16

__global__ __launch_bounds__(256, 4)
void fm_layer_kernel(const float* __restrict__ dense,
                     const int*   __restrict__ sparse,
                     const float* __restrict__ w0,
                     const float* __restrict__ w,
                     const float* __restrict__ V,
                     float*       __restrict__ out)
{
    const int gt = blockIdx.x * blockDim.x + threadIdx.x;
    const int b  = gt >> 4;        // batch row
    const int k  = gt & 15;        // latent dim handled by this lane
    if (b >= FM_BATCH) return;

    const int*   sp = sparse + b * FM_NFIELDS;
    const float* db = dense  + b * FM_NDENSE;
    const float* Vk = V + (size_t)k * FM_FEATNUM;

    // ---- gather indices (same address across the 16-lane group -> broadcast) ----
    int idx[FM_NFIELDS];
#pragma unroll
    for (int j = 0; j < FM_NFIELDS; j++)
        idx[j] = FM_NDENSE + j * FM_PERFIELD + __ldg(sp + j);

    // ---- issue all 26 scattered V gathers up-front (MLP ~ 26) ----
    float g[FM_NFIELDS];
#pragma unroll
    for (int j = 0; j < FM_NFIELDS; j++)
        g[j] = __ldg(Vk + idx[j]);

    // ---- first-order w gathers, spread across lanes: fields j = k and k+16 ----
    float fo = __ldg(w + idx[0] - idx[0] + FM_NDENSE + k * FM_PERFIELD + __ldg(sp + k));
    if (k + 16 < FM_NFIELDS) {
        const int j2 = k + 16;
        fo += __ldg(w + FM_NDENSE + j2 * FM_PERFIELD + __ldg(sp + j2));
    }
    if (k < FM_NDENSE)
        fo = fmaf(__ldg(db + k), __ldg(w + k), fo);

    // ---- accumulate e_k and sq_k from the gathered values ----
    float e = 0.0f, s = 0.0f;
#pragma unroll
    for (int j = 0; j < FM_NFIELDS; j++) {
        e += g[j];
        s = fmaf(g[j], g[j], s);
    }

    // dense contribution (V[k,0:13] is tiny and cache-resident)
#pragma unroll
    for (int d = 0; d < FM_NDENSE; d++) {
        const float x  = __ldg(db + d);
        const float v  = __ldg(Vk + d);
        e = fmaf(x, v, e);
        const float xv = x * v;
        s = fmaf(xv, xv, s);
    }

    float tot = fmaf(0.5f, e * e - s, fo);   // 0.5*(e^2 - sq) + first-order part

    // ---- reduce over the 16 lanes of this row (xor distance < 16 stays in group) ----
#pragma unroll
    for (int m = 8; m >= 1; m >>= 1)
        tot += __shfl_xor_sync(0xFFFFFFFFu, tot, m);

    if (k == 0)
        out[b] = tot + __ldg(w0);
}

extern "C" void kernel_launch(void* const* d_in, const int* in_sizes, int n_in,
                              void* d_out, int out_size)
{
    const float* dense  = (const float*)d_in[0];
    const int*   sparse = (const int*)  d_in[1];
    const float* w0     = (const float*)d_in[2];
    const float* w      = (const float*)d_in[3];
    const float* V      = (const float*)d_in[4];
    float*       out    = (float*)d_out;

    const int total   = FM_BATCH * FM_K;      // 65536 threads
    const int threads = 256;
    const int blocks  = (total + threads - 1) / threads;  // 256 blocks
    fm_layer_kernel<<<blocks, threads>>>(dense, sparse, w0, w, V, out);
}